// round 11
// baseline (speedup 1.0000x reference)
#include <cuda_runtime.h>
#include <cstdint>

// ---------------------------------------------------------------------------
// AdjGenerator: adj = (mean_h sigmoid(log(relu(Wg·PE)+1e-6) + (q·kT)/32) > 0.5)
// N = M = 2048, D = 1024, EMB = 64, HEADS = 16
// ---------------------------------------------------------------------------

#define NDIM 2048
#define MDIM 2048
#define DDIM 1024
#define EMB  64
#define HEADS 16

__device__ float g_q[NDIM * DDIM];
__device__ float g_k[MDIM * DDIM];
__device__ float g_aff[NDIM * MDIM];

typedef unsigned long long ull;

// ---- packed f32x2 helpers (Blackwell FFMA2, PTX-only) ---------------------
__device__ __forceinline__ ull dup2(float v) {
    ull r;
    asm("mov.b64 %0, {%1, %1};" : "=l"(r) : "f"(v));
    return r;
}
__device__ __forceinline__ void fma2(ull& d, ull a, ull b) {
    asm("fma.rn.f32x2 %0, %1, %2, %0;" : "+l"(d) : "l"(a), "l"(b));
}
__device__ __forceinline__ float2 unpack2(ull v) {
    float2 f;
    asm("mov.b64 {%0, %1}, %2;" : "=f"(f.x), "=f"(f.y) : "l"(v));
    return f;
}
// streaming (evict-first) 16B global load
__device__ __forceinline__ void ldcs_v2u64(const void* p, ull& a, ull& b) {
    asm("ld.global.cs.v2.u64 {%0, %1}, [%2];" : "=l"(a), "=l"(b) : "l"(p));
}

// ---------------------------------------------------------------------------
// SGEMM NT (unchanged from R10 — verified 174us/launch, fma 65%).
// 512 threads, BM=128, BN=256, BK=16, row-packed f32x2 accumulators,
// float B smem with reg-side dup (alu pipe), double-buffered, 1 bar/chunk.
// ---------------------------------------------------------------------------
#define BM 128
#define BN 256
#define BK 16
#define BH 128   /* BN/2 */
#define NCHUNK (DDIM / BK)

__global__ void __launch_bounds__(512, 1)
gemm_nt_kernel(const float* __restrict__ A0, const float* __restrict__ B0,
               const float* __restrict__ bias0,
               const float* __restrict__ A1, const float* __restrict__ B1,
               const float* __restrict__ bias1,
               int Ncols, float scale, int outsel)
{
    const float* A;
    const float* B;
    const float* bias;
    float* C;
    if (outsel == 0) {
        if (blockIdx.z == 0) { A = A0; B = B0; bias = bias0; C = g_q; }
        else                 { A = A1; B = B1; bias = bias1; C = g_k; }
    } else {
        A = g_q; B = g_k; bias = nullptr; C = g_aff;
    }

    const int K = DDIM;

    __shared__ float As[2][BK][BM + 4];   // 16.9 KB
    __shared__ float Bs[2][BK][BN + 4];   // 33.3 KB

    const int tid = threadIdx.x;
    const int tx = tid & 31;
    const int ty = tid >> 5;
    const int row0 = blockIdx.y * BM;
    const int col0 = blockIdx.x * BN;

    const float* Abase = A + (size_t)row0 * K;
    const float* Bbase = B + (size_t)col0 * K;

    const int ar0 = tid >> 2,          ac0 = (tid & 3) * 4;
    const int br1 = (tid + 512) >> 2,  bc1 = ((tid + 512) & 3) * 4;

    float4 av0 = *(const float4*)&Abase[(size_t)ar0 * K + ac0];
    float4 bv0 = *(const float4*)&Bbase[(size_t)ar0 * K + ac0];
    float4 bv1 = *(const float4*)&Bbase[(size_t)br1 * K + bc1];

    As[0][ac0 + 0][ar0] = av0.x; As[0][ac0 + 1][ar0] = av0.y;
    As[0][ac0 + 2][ar0] = av0.z; As[0][ac0 + 3][ar0] = av0.w;
    Bs[0][ac0 + 0][ar0] = bv0.x; Bs[0][ac0 + 1][ar0] = bv0.y;
    Bs[0][ac0 + 2][ar0] = bv0.z; Bs[0][ac0 + 3][ar0] = bv0.w;
    Bs[0][bc1 + 0][br1] = bv1.x; Bs[0][bc1 + 1][br1] = bv1.y;
    Bs[0][bc1 + 2][br1] = bv1.z; Bs[0][bc1 + 3][br1] = bv1.w;
    __syncthreads();

    ull c2[4][8];   // [row-pair][col]
#pragma unroll
    for (int i = 0; i < 4; i++)
#pragma unroll
        for (int j = 0; j < 8; j++) c2[i][j] = 0ull;

    int s = 0;
    for (int c = 0; c < NCHUNK; c++) {
        const int kc = (c + 1) * BK;
        if (c + 1 < NCHUNK) {
            av0 = *(const float4*)&Abase[(size_t)ar0 * K + kc + ac0];
            bv0 = *(const float4*)&Bbase[(size_t)ar0 * K + kc + ac0];
            bv1 = *(const float4*)&Bbase[(size_t)br1 * K + kc + bc1];
        }
#pragma unroll
        for (int k = 0; k < BK; k++) {
            ulonglong2 aA = *(const ulonglong2*)&As[s][k][ty * 8];
            ulonglong2 aB = *(const ulonglong2*)&As[s][k][ty * 8 + 4];
            ull a2[4] = { aA.x, aA.y, aB.x, aB.y };
            float4 f0 = *(const float4*)&Bs[s][k][tx * 4];
            float4 f1 = *(const float4*)&Bs[s][k][BH + tx * 4];
            ull b2[8];
            b2[0] = dup2(f0.x); b2[1] = dup2(f0.y); b2[2] = dup2(f0.z); b2[3] = dup2(f0.w);
            b2[4] = dup2(f1.x); b2[5] = dup2(f1.y); b2[6] = dup2(f1.z); b2[7] = dup2(f1.w);
#pragma unroll
            for (int i = 0; i < 4; i++) {
#pragma unroll
                for (int j = 0; j < 8; j++) fma2(c2[i][j], a2[i], b2[j]);
            }
        }
        if (c + 1 < NCHUNK) {
            const int t = s ^ 1;
            As[t][ac0 + 0][ar0] = av0.x; As[t][ac0 + 1][ar0] = av0.y;
            As[t][ac0 + 2][ar0] = av0.z; As[t][ac0 + 3][ar0] = av0.w;
            Bs[t][ac0 + 0][ar0] = bv0.x; Bs[t][ac0 + 1][ar0] = bv0.y;
            Bs[t][ac0 + 2][ar0] = bv0.z; Bs[t][ac0 + 3][ar0] = bv0.w;
            Bs[t][bc1 + 0][br1] = bv1.x; Bs[t][bc1 + 1][br1] = bv1.y;
            Bs[t][bc1 + 2][br1] = bv1.z; Bs[t][bc1 + 3][br1] = bv1.w;
            __syncthreads();
            s = t;
        }
    }

    float4 bv_lo, bv_hi;
    if (bias) {
        bv_lo = *(const float4*)&bias[col0 + tx * 4];
        bv_hi = *(const float4*)&bias[col0 + BH + tx * 4];
    }
#pragma unroll
    for (int i2 = 0; i2 < 4; i2++) {
        size_t r = (size_t)(row0 + ty * 8 + 2 * i2);
        float* rlo = C + r * (size_t)Ncols + col0;
        float* rhi = rlo + Ncols;
        float2 p0 = unpack2(c2[i2][0]);
        float2 p1 = unpack2(c2[i2][1]);
        float2 p2 = unpack2(c2[i2][2]);
        float2 p3 = unpack2(c2[i2][3]);
        float2 p4 = unpack2(c2[i2][4]);
        float2 p5 = unpack2(c2[i2][5]);
        float2 p6 = unpack2(c2[i2][6]);
        float2 p7 = unpack2(c2[i2][7]);
        float4 lo0, lo1, hi0, hi1;
        if (bias) {
            lo0 = make_float4(p0.x * scale + bv_lo.x, p1.x * scale + bv_lo.y,
                              p2.x * scale + bv_lo.z, p3.x * scale + bv_lo.w);
            hi0 = make_float4(p0.y * scale + bv_lo.x, p1.y * scale + bv_lo.y,
                              p2.y * scale + bv_lo.z, p3.y * scale + bv_lo.w);
            lo1 = make_float4(p4.x * scale + bv_hi.x, p5.x * scale + bv_hi.y,
                              p6.x * scale + bv_hi.z, p7.x * scale + bv_hi.w);
            hi1 = make_float4(p4.y * scale + bv_hi.x, p5.y * scale + bv_hi.y,
                              p6.y * scale + bv_hi.z, p7.y * scale + bv_hi.w);
        } else {
            lo0 = make_float4(p0.x * scale, p1.x * scale, p2.x * scale, p3.x * scale);
            hi0 = make_float4(p0.y * scale, p1.y * scale, p2.y * scale, p3.y * scale);
            lo1 = make_float4(p4.x * scale, p5.x * scale, p6.x * scale, p7.x * scale);
            hi1 = make_float4(p4.y * scale, p5.y * scale, p6.y * scale, p7.y * scale);
        }
        *(float4*)&rlo[tx * 4]      = lo0;
        *(float4*)&rlo[BH + tx * 4] = lo1;
        *(float4*)&rhi[tx * 4]      = hi0;
        *(float4*)&rhi[BH + tx * 4] = hi1;
    }
}

// ---------------------------------------------------------------------------
// Pos-gate stream + fused epilogue.
// R11 change: 3 CTAs/SM (24 warps) for +50% latency hiding & fma capacity,
// financed by prefetch depth 4 -> 2 (frees 8 regs; ~82 total <= 85 cap).
// Outstanding: 24 warps x 2 x 16B = 24KB/SM > 18.5KB needed at 32 B/cyc.
// ---------------------------------------------------------------------------
__global__ void __launch_bounds__(256, 3)
pos_epilogue_kernel(const float* __restrict__ PE, const float* __restrict__ Wg_w,
                    const float* __restrict__ Wg_b, float* __restrict__ out)
{
    __shared__ ull sh_wg2[EMB][HEADS];   // dup'd f32x2 per (e, h), 8 KB
    __shared__ float sh_b[HEADS];

    const int tid = threadIdx.x;
    for (int idx = tid; idx < EMB * HEADS; idx += 256) {
        int e = idx >> 4, h = idx & 15;
        sh_wg2[e][h] = dup2(Wg_w[h * EMB + e]);
    }
    if (tid < HEADS) sh_b[tid] = Wg_b[tid];
    __syncthreads();

    const int n = blockIdx.y;
    const int m = blockIdx.x * 1024 + tid * 4;

    const char* pe = (const char*)(PE + (size_t)n * MDIM + m);
    const size_t PLANE = (size_t)NDIM * MDIM * 4;   // bytes

    ull acc[HEADS][2];
#pragma unroll
    for (int h = 0; h < HEADS; h++) { acc[h][0] = 0ull; acc[h][1] = 0ull; }

    // depth-2 software pipeline of 16B streaming loads
    ull bx[2], by[2];
#pragma unroll
    for (int i = 0; i < 2; i++) ldcs_v2u64(pe + (size_t)i * PLANE, bx[i], by[i]);

    for (int eo = 0; eo < EMB; eo += 2) {
#pragma unroll
        for (int i = 0; i < 2; i++) {
            ull pvx = bx[i], pvy = by[i];
            int en_ = eo + 2 + i;
            if (en_ < EMB) ldcs_v2u64(pe + (size_t)en_ * PLANE, bx[i], by[i]);
            const ulonglong2* wrow = (const ulonglong2*)sh_wg2[eo + i];
#pragma unroll
            for (int h2 = 0; h2 < 8; h2++) {
                ulonglong2 w = wrow[h2];          // LDS.128: 2 heads
                fma2(acc[2 * h2][0],     w.x, pvx);
                fma2(acc[2 * h2][1],     w.x, pvy);
                fma2(acc[2 * h2 + 1][0], w.y, pvx);
                fma2(acc[2 * h2 + 1][1], w.y, pvy);
            }
        }
    }

    const float4 av = *(const float4*)&g_aff[(size_t)n * MDIM + m];
    const float L2E = 1.4426950408889634f;
    float en0 = exp2f(-av.x * L2E);
    float en1 = exp2f(-av.y * L2E);
    float en2 = exp2f(-av.z * L2E);
    float en3 = exp2f(-av.w * L2E);

    float s0 = 0.f, s1 = 0.f, s2 = 0.f, s3 = 0.f;
#pragma unroll
    for (int h = 0; h < HEADS; h++) {
        float bh = sh_b[h];
        float2 p0 = unpack2(acc[h][0]);
        float2 p1 = unpack2(acc[h][1]);
        float w;
        w = fmaxf(p0.x + bh, 0.f) + 1e-6f; s0 += __fdividef(w, w + en0);
        w = fmaxf(p0.y + bh, 0.f) + 1e-6f; s1 += __fdividef(w, w + en1);
        w = fmaxf(p1.x + bh, 0.f) + 1e-6f; s2 += __fdividef(w, w + en2);
        w = fmaxf(p1.y + bh, 0.f) + 1e-6f; s3 += __fdividef(w, w + en3);
    }

    float4 o;
    o.x = (s0 > 8.0f) ? 1.0f : 0.0f;
    o.y = (s1 > 8.0f) ? 1.0f : 0.0f;
    o.z = (s2 > 8.0f) ? 1.0f : 0.0f;
    o.w = (s3 > 8.0f) ? 1.0f : 0.0f;
    *(float4*)&out[(size_t)n * MDIM + m] = o;
}

// ---------------------------------------------------------------------------
extern "C" void kernel_launch(void* const* d_in, const int* in_sizes, int n_in,
                              void* d_out, int out_size)
{
    (void)in_sizes; (void)n_in; (void)out_size;
    const float* ref_feat = (const float*)d_in[0];
    const float* sup_feat = (const float*)d_in[1];
    const float* PE       = (const float*)d_in[2];
    const float* Wg_w     = (const float*)d_in[3];
    const float* Wg_b     = (const float*)d_in[4];
    const float* Wq_w     = (const float*)d_in[5];
    const float* Wq_b     = (const float*)d_in[6];
    const float* Wk_w     = (const float*)d_in[7];
    const float* Wk_b     = (const float*)d_in[8];
    float* out = (float*)d_out;

    // fused q/k GEMM: z=0 -> q = ref@WqT+bq, z=1 -> k = sup@WkT+bk
    gemm_nt_kernel<<<dim3(DDIM / BN, NDIM / BM, 2), 512>>>(
        ref_feat, Wq_w, Wq_b, sup_feat, Wk_w, Wk_b, DDIM, 1.0f, 0);
    // aff = (q @ kT) / 32
    gemm_nt_kernel<<<dim3(MDIM / BN, NDIM / BM, 1), 512>>>(
        nullptr, nullptr, nullptr, nullptr, nullptr, nullptr, MDIM, 0.03125f, 2);
    // pos stream + fused epilogue
    pos_epilogue_kernel<<<dim3(MDIM / 1024, NDIM), 256>>>(PE, Wg_w, Wg_b, out);
}

// round 12
// speedup vs baseline: 1.3581x; 1.3581x over previous
#include <cuda_runtime.h>
#include <cstdint>

// ---------------------------------------------------------------------------
// AdjGenerator: adj = (mean_h sigmoid(log(relu(Wg·PE)+1e-6) + (q·kT)/32) > 0.5)
// N = M = 2048, D = 1024, EMB = 64, HEADS = 16
// ---------------------------------------------------------------------------

#define NDIM 2048
#define MDIM 2048
#define DDIM 1024
#define EMB  64
#define HEADS 16

__device__ float g_q[NDIM * DDIM];
__device__ float g_k[MDIM * DDIM];
__device__ float g_aff[NDIM * MDIM];

typedef unsigned long long ull;

// ---- packed f32x2 helpers (Blackwell FFMA2, PTX-only) ---------------------
__device__ __forceinline__ ull dup2(float v) {
    ull r;
    asm("mov.b64 %0, {%1, %1};" : "=l"(r) : "f"(v));
    return r;
}
__device__ __forceinline__ void fma2(ull& d, ull a, ull b) {
    asm("fma.rn.f32x2 %0, %1, %2, %0;" : "+l"(d) : "l"(a), "l"(b));
}
__device__ __forceinline__ float2 unpack2(ull v) {
    float2 f;
    asm("mov.b64 {%0, %1}, %2;" : "=f"(f.x), "=f"(f.y) : "l"(v));
    return f;
}
// streaming (evict-first) 16B global load
__device__ __forceinline__ void ldcs_v2u64(const void* p, ull& a, ull& b) {
    asm("ld.global.cs.v2.u64 {%0, %1}, [%2];" : "=l"(a), "=l"(b) : "l"(p));
}

// ---------------------------------------------------------------------------
// SGEMM NT (unchanged from R10 — verified ~170us/launch, fma 65%).
// 512 threads, BM=128, BN=256, BK=16, row-packed f32x2 accumulators,
// float B smem with reg-side dup (alu pipe), double-buffered, 1 bar/chunk.
// ---------------------------------------------------------------------------
#define BM 128
#define BN 256
#define BK 16
#define BH 128   /* BN/2 */
#define NCHUNK (DDIM / BK)

__global__ void __launch_bounds__(512, 1)
gemm_nt_kernel(const float* __restrict__ A0, const float* __restrict__ B0,
               const float* __restrict__ bias0,
               const float* __restrict__ A1, const float* __restrict__ B1,
               const float* __restrict__ bias1,
               int Ncols, float scale, int outsel)
{
    const float* A;
    const float* B;
    const float* bias;
    float* C;
    if (outsel == 0) {
        if (blockIdx.z == 0) { A = A0; B = B0; bias = bias0; C = g_q; }
        else                 { A = A1; B = B1; bias = bias1; C = g_k; }
    } else {
        A = g_q; B = g_k; bias = nullptr; C = g_aff;
    }

    const int K = DDIM;

    __shared__ float As[2][BK][BM + 4];   // 16.9 KB
    __shared__ float Bs[2][BK][BN + 4];   // 33.3 KB

    const int tid = threadIdx.x;
    const int tx = tid & 31;
    const int ty = tid >> 5;
    const int row0 = blockIdx.y * BM;
    const int col0 = blockIdx.x * BN;

    const float* Abase = A + (size_t)row0 * K;
    const float* Bbase = B + (size_t)col0 * K;

    const int ar0 = tid >> 2,          ac0 = (tid & 3) * 4;
    const int br1 = (tid + 512) >> 2,  bc1 = ((tid + 512) & 3) * 4;

    float4 av0 = *(const float4*)&Abase[(size_t)ar0 * K + ac0];
    float4 bv0 = *(const float4*)&Bbase[(size_t)ar0 * K + ac0];
    float4 bv1 = *(const float4*)&Bbase[(size_t)br1 * K + bc1];

    As[0][ac0 + 0][ar0] = av0.x; As[0][ac0 + 1][ar0] = av0.y;
    As[0][ac0 + 2][ar0] = av0.z; As[0][ac0 + 3][ar0] = av0.w;
    Bs[0][ac0 + 0][ar0] = bv0.x; Bs[0][ac0 + 1][ar0] = bv0.y;
    Bs[0][ac0 + 2][ar0] = bv0.z; Bs[0][ac0 + 3][ar0] = bv0.w;
    Bs[0][bc1 + 0][br1] = bv1.x; Bs[0][bc1 + 1][br1] = bv1.y;
    Bs[0][bc1 + 2][br1] = bv1.z; Bs[0][bc1 + 3][br1] = bv1.w;
    __syncthreads();

    ull c2[4][8];   // [row-pair][col]
#pragma unroll
    for (int i = 0; i < 4; i++)
#pragma unroll
        for (int j = 0; j < 8; j++) c2[i][j] = 0ull;

    int s = 0;
    for (int c = 0; c < NCHUNK; c++) {
        const int kc = (c + 1) * BK;
        if (c + 1 < NCHUNK) {
            av0 = *(const float4*)&Abase[(size_t)ar0 * K + kc + ac0];
            bv0 = *(const float4*)&Bbase[(size_t)ar0 * K + kc + ac0];
            bv1 = *(const float4*)&Bbase[(size_t)br1 * K + kc + bc1];
        }
#pragma unroll
        for (int k = 0; k < BK; k++) {
            ulonglong2 aA = *(const ulonglong2*)&As[s][k][ty * 8];
            ulonglong2 aB = *(const ulonglong2*)&As[s][k][ty * 8 + 4];
            ull a2[4] = { aA.x, aA.y, aB.x, aB.y };
            float4 f0 = *(const float4*)&Bs[s][k][tx * 4];
            float4 f1 = *(const float4*)&Bs[s][k][BH + tx * 4];
            ull b2[8];
            b2[0] = dup2(f0.x); b2[1] = dup2(f0.y); b2[2] = dup2(f0.z); b2[3] = dup2(f0.w);
            b2[4] = dup2(f1.x); b2[5] = dup2(f1.y); b2[6] = dup2(f1.z); b2[7] = dup2(f1.w);
#pragma unroll
            for (int i = 0; i < 4; i++) {
#pragma unroll
                for (int j = 0; j < 8; j++) fma2(c2[i][j], a2[i], b2[j]);
            }
        }
        if (c + 1 < NCHUNK) {
            const int t = s ^ 1;
            As[t][ac0 + 0][ar0] = av0.x; As[t][ac0 + 1][ar0] = av0.y;
            As[t][ac0 + 2][ar0] = av0.z; As[t][ac0 + 3][ar0] = av0.w;
            Bs[t][ac0 + 0][ar0] = bv0.x; Bs[t][ac0 + 1][ar0] = bv0.y;
            Bs[t][ac0 + 2][ar0] = bv0.z; Bs[t][ac0 + 3][ar0] = bv0.w;
            Bs[t][bc1 + 0][br1] = bv1.x; Bs[t][bc1 + 1][br1] = bv1.y;
            Bs[t][bc1 + 2][br1] = bv1.z; Bs[t][bc1 + 3][br1] = bv1.w;
            __syncthreads();
            s = t;
        }
    }

    float4 bv_lo, bv_hi;
    if (bias) {
        bv_lo = *(const float4*)&bias[col0 + tx * 4];
        bv_hi = *(const float4*)&bias[col0 + BH + tx * 4];
    }
#pragma unroll
    for (int i2 = 0; i2 < 4; i2++) {
        size_t r = (size_t)(row0 + ty * 8 + 2 * i2);
        float* rlo = C + r * (size_t)Ncols + col0;
        float* rhi = rlo + Ncols;
        float2 p0 = unpack2(c2[i2][0]);
        float2 p1 = unpack2(c2[i2][1]);
        float2 p2 = unpack2(c2[i2][2]);
        float2 p3 = unpack2(c2[i2][3]);
        float2 p4 = unpack2(c2[i2][4]);
        float2 p5 = unpack2(c2[i2][5]);
        float2 p6 = unpack2(c2[i2][6]);
        float2 p7 = unpack2(c2[i2][7]);
        float4 lo0, lo1, hi0, hi1;
        if (bias) {
            lo0 = make_float4(p0.x * scale + bv_lo.x, p1.x * scale + bv_lo.y,
                              p2.x * scale + bv_lo.z, p3.x * scale + bv_lo.w);
            hi0 = make_float4(p0.y * scale + bv_lo.x, p1.y * scale + bv_lo.y,
                              p2.y * scale + bv_lo.z, p3.y * scale + bv_lo.w);
            lo1 = make_float4(p4.x * scale + bv_hi.x, p5.x * scale + bv_hi.y,
                              p6.x * scale + bv_hi.z, p7.x * scale + bv_hi.w);
            hi1 = make_float4(p4.y * scale + bv_hi.x, p5.y * scale + bv_hi.y,
                              p6.y * scale + bv_hi.z, p7.y * scale + bv_hi.w);
        } else {
            lo0 = make_float4(p0.x * scale, p1.x * scale, p2.x * scale, p3.x * scale);
            hi0 = make_float4(p0.y * scale, p1.y * scale, p2.y * scale, p3.y * scale);
            lo1 = make_float4(p4.x * scale, p5.x * scale, p6.x * scale, p7.x * scale);
            hi1 = make_float4(p4.y * scale, p5.y * scale, p6.y * scale, p7.y * scale);
        }
        *(float4*)&rlo[tx * 4]      = lo0;
        *(float4*)&rlo[BH + tx * 4] = lo1;
        *(float4*)&rhi[tx * 4]      = hi0;
        *(float4*)&rhi[BH + tx * 4] = hi1;
    }
}

// ---------------------------------------------------------------------------
// Pos-gate stream + fused epilogue.
// R12: back to the verified R10 config — T=4, __launch_bounds__(256,2)
// (T=4 does NOT fit under 85 regs; 3 CTAs/SM caused inner-loop spills in R11).
// Single change vs R10: prefetch depth 4 -> 6 (16w x 6 x 16B = 24KB/SM
// outstanding > 18.5KB needed to cover 577-cyc DRAM at 32 B/cyc).
// ---------------------------------------------------------------------------
#define PDEPTH 6

__global__ void __launch_bounds__(256, 2)
pos_epilogue_kernel(const float* __restrict__ PE, const float* __restrict__ Wg_w,
                    const float* __restrict__ Wg_b, float* __restrict__ out)
{
    __shared__ ull sh_wg2[EMB + 2][HEADS];   // dup'd f32x2 per (e, h)
    __shared__ float sh_b[HEADS];

    const int tid = threadIdx.x;
    for (int idx = tid; idx < EMB * HEADS; idx += 256) {
        int e = idx >> 4, h = idx & 15;
        sh_wg2[e][h] = dup2(Wg_w[h * EMB + e]);
    }
    if (tid < HEADS) sh_b[tid] = Wg_b[tid];
    // zero-pad planes EMB..EMB+1 so the tail iterations are harmless
    if (tid < 2 * HEADS) sh_wg2[EMB + (tid >> 4)][tid & 15] = 0ull;
    __syncthreads();

    const int n = blockIdx.y;
    const int m = blockIdx.x * 1024 + tid * 4;

    const char* pe = (const char*)(PE + (size_t)n * MDIM + m);
    const size_t PLANE = (size_t)NDIM * MDIM * 4;   // bytes

    ull acc[HEADS][2];
#pragma unroll
    for (int h = 0; h < HEADS; h++) { acc[h][0] = 0ull; acc[h][1] = 0ull; }

    // depth-6 software pipeline of 16B streaming loads
    ull bx[PDEPTH], by[PDEPTH];
#pragma unroll
    for (int i = 0; i < PDEPTH; i++) ldcs_v2u64(pe + (size_t)i * PLANE, bx[i], by[i]);

    // EMB=64, PDEPTH=6: iterate 66 plane-slots (last 2 use zero weights);
    // loads are guarded so nothing reads past plane 63.
    for (int eo = 0; eo < 66; eo += PDEPTH) {
#pragma unroll
        for (int i = 0; i < PDEPTH; i++) {
            const int e = eo + i;
            if (e >= 66) break;
            ull pvx = bx[i], pvy = by[i];
            int en_ = e + PDEPTH;
            if (en_ < EMB) ldcs_v2u64(pe + (size_t)en_ * PLANE, bx[i], by[i]);
            const ulonglong2* wrow = (const ulonglong2*)sh_wg2[e < EMB ? e : EMB];
#pragma unroll
            for (int h2 = 0; h2 < 8; h2++) {
                ulonglong2 w = wrow[h2];          // LDS.128: 2 heads
                fma2(acc[2 * h2][0],     w.x, pvx);
                fma2(acc[2 * h2][1],     w.x, pvy);
                fma2(acc[2 * h2 + 1][0], w.y, pvx);
                fma2(acc[2 * h2 + 1][1], w.y, pvy);
            }
        }
    }

    const float4 av = *(const float4*)&g_aff[(size_t)n * MDIM + m];
    const float L2E = 1.4426950408889634f;
    float en0 = exp2f(-av.x * L2E);
    float en1 = exp2f(-av.y * L2E);
    float en2 = exp2f(-av.z * L2E);
    float en3 = exp2f(-av.w * L2E);

    float s0 = 0.f, s1 = 0.f, s2 = 0.f, s3 = 0.f;
#pragma unroll
    for (int h = 0; h < HEADS; h++) {
        float bh = sh_b[h];
        float2 p0 = unpack2(acc[h][0]);
        float2 p1 = unpack2(acc[h][1]);
        float w;
        w = fmaxf(p0.x + bh, 0.f) + 1e-6f; s0 += __fdividef(w, w + en0);
        w = fmaxf(p0.y + bh, 0.f) + 1e-6f; s1 += __fdividef(w, w + en1);
        w = fmaxf(p1.x + bh, 0.f) + 1e-6f; s2 += __fdividef(w, w + en2);
        w = fmaxf(p1.y + bh, 0.f) + 1e-6f; s3 += __fdividef(w, w + en3);
    }

    float4 o;
    o.x = (s0 > 8.0f) ? 1.0f : 0.0f;
    o.y = (s1 > 8.0f) ? 1.0f : 0.0f;
    o.z = (s2 > 8.0f) ? 1.0f : 0.0f;
    o.w = (s3 > 8.0f) ? 1.0f : 0.0f;
    *(float4*)&out[(size_t)n * MDIM + m] = o;
}

// ---------------------------------------------------------------------------
extern "C" void kernel_launch(void* const* d_in, const int* in_sizes, int n_in,
                              void* d_out, int out_size)
{
    (void)in_sizes; (void)n_in; (void)out_size;
    const float* ref_feat = (const float*)d_in[0];
    const float* sup_feat = (const float*)d_in[1];
    const float* PE       = (const float*)d_in[2];
    const float* Wg_w     = (const float*)d_in[3];
    const float* Wg_b     = (const float*)d_in[4];
    const float* Wq_w     = (const float*)d_in[5];
    const float* Wq_b     = (const float*)d_in[6];
    const float* Wk_w     = (const float*)d_in[7];
    const float* Wk_b     = (const float*)d_in[8];
    float* out = (float*)d_out;

    // fused q/k GEMM: z=0 -> q = ref@WqT+bq, z=1 -> k = sup@WkT+bk
    gemm_nt_kernel<<<dim3(DDIM / BN, NDIM / BM, 2), 512>>>(
        ref_feat, Wq_w, Wq_b, sup_feat, Wk_w, Wk_b, DDIM, 1.0f, 0);
    // aff = (q @ kT) / 32
    gemm_nt_kernel<<<dim3(MDIM / BN, NDIM / BM, 1), 512>>>(
        nullptr, nullptr, nullptr, nullptr, nullptr, nullptr, MDIM, 0.03125f, 2);
    // pos stream + fused epilogue
    pos_epilogue_kernel<<<dim3(MDIM / 1024, NDIM), 256>>>(PE, Wg_w, Wg_b, out);
}

// round 13
// speedup vs baseline: 1.4232x; 1.0479x over previous
#include <cuda_runtime.h>
#include <cstdint>

// ---------------------------------------------------------------------------
// AdjGenerator: adj = (mean_h sigmoid(log(relu(Wg·PE)+1e-6) + (q·kT)/32) > 0.5)
// N = M = 2048, D = 1024, EMB = 64, HEADS = 16
// ---------------------------------------------------------------------------

#define NDIM 2048
#define MDIM 2048
#define DDIM 1024
#define EMB  64
#define HEADS 16

__device__ float g_q[NDIM * DDIM];
__device__ float g_k[MDIM * DDIM];
__device__ float g_aff[NDIM * MDIM];

typedef unsigned long long ull;

// ---- packed f32x2 helpers (Blackwell FFMA2, PTX-only) ---------------------
__device__ __forceinline__ ull dup2(float v) {
    ull r;
    asm("mov.b64 %0, {%1, %1};" : "=l"(r) : "f"(v));
    return r;
}
__device__ __forceinline__ void fma2(ull& d, ull a, ull b) {
    asm("fma.rn.f32x2 %0, %1, %2, %0;" : "+l"(d) : "l"(a), "l"(b));
}
__device__ __forceinline__ float2 unpack2(ull v) {
    float2 f;
    asm("mov.b64 {%0, %1}, %2;" : "=f"(f.x), "=f"(f.y) : "l"(v));
    return f;
}
// streaming (evict-first) 16B global load
__device__ __forceinline__ void ldcs_v2u64(const void* p, ull& a, ull& b) {
    asm("ld.global.cs.v2.u64 {%0, %1}, [%2];" : "=l"(a), "=l"(b) : "l"(p));
}

// ---------------------------------------------------------------------------
// SGEMM NT (unchanged from R10/R12 — verified ~165us/launch, fma 65%).
// 512 threads, BM=128, BN=256, BK=16, row-packed f32x2 accumulators,
// float B smem with reg-side dup (alu pipe), double-buffered, 1 bar/chunk.
// ---------------------------------------------------------------------------
#define BM 128
#define BN 256
#define BK 16
#define BH 128   /* BN/2 */
#define NCHUNK (DDIM / BK)

__global__ void __launch_bounds__(512, 1)
gemm_nt_kernel(const float* __restrict__ A0, const float* __restrict__ B0,
               const float* __restrict__ bias0,
               const float* __restrict__ A1, const float* __restrict__ B1,
               const float* __restrict__ bias1,
               int Ncols, float scale, int outsel)
{
    const float* A;
    const float* B;
    const float* bias;
    float* C;
    if (outsel == 0) {
        if (blockIdx.z == 0) { A = A0; B = B0; bias = bias0; C = g_q; }
        else                 { A = A1; B = B1; bias = bias1; C = g_k; }
    } else {
        A = g_q; B = g_k; bias = nullptr; C = g_aff;
    }

    const int K = DDIM;

    __shared__ float As[2][BK][BM + 4];   // 16.9 KB
    __shared__ float Bs[2][BK][BN + 4];   // 33.3 KB

    const int tid = threadIdx.x;
    const int tx = tid & 31;
    const int ty = tid >> 5;
    const int row0 = blockIdx.y * BM;
    const int col0 = blockIdx.x * BN;

    const float* Abase = A + (size_t)row0 * K;
    const float* Bbase = B + (size_t)col0 * K;

    const int ar0 = tid >> 2,          ac0 = (tid & 3) * 4;
    const int br1 = (tid + 512) >> 2,  bc1 = ((tid + 512) & 3) * 4;

    float4 av0 = *(const float4*)&Abase[(size_t)ar0 * K + ac0];
    float4 bv0 = *(const float4*)&Bbase[(size_t)ar0 * K + ac0];
    float4 bv1 = *(const float4*)&Bbase[(size_t)br1 * K + bc1];

    As[0][ac0 + 0][ar0] = av0.x; As[0][ac0 + 1][ar0] = av0.y;
    As[0][ac0 + 2][ar0] = av0.z; As[0][ac0 + 3][ar0] = av0.w;
    Bs[0][ac0 + 0][ar0] = bv0.x; Bs[0][ac0 + 1][ar0] = bv0.y;
    Bs[0][ac0 + 2][ar0] = bv0.z; Bs[0][ac0 + 3][ar0] = bv0.w;
    Bs[0][bc1 + 0][br1] = bv1.x; Bs[0][bc1 + 1][br1] = bv1.y;
    Bs[0][bc1 + 2][br1] = bv1.z; Bs[0][bc1 + 3][br1] = bv1.w;
    __syncthreads();

    ull c2[4][8];   // [row-pair][col]
#pragma unroll
    for (int i = 0; i < 4; i++)
#pragma unroll
        for (int j = 0; j < 8; j++) c2[i][j] = 0ull;

    int s = 0;
    for (int c = 0; c < NCHUNK; c++) {
        const int kc = (c + 1) * BK;
        if (c + 1 < NCHUNK) {
            av0 = *(const float4*)&Abase[(size_t)ar0 * K + kc + ac0];
            bv0 = *(const float4*)&Bbase[(size_t)ar0 * K + kc + ac0];
            bv1 = *(const float4*)&Bbase[(size_t)br1 * K + kc + bc1];
        }
#pragma unroll
        for (int k = 0; k < BK; k++) {
            ulonglong2 aA = *(const ulonglong2*)&As[s][k][ty * 8];
            ulonglong2 aB = *(const ulonglong2*)&As[s][k][ty * 8 + 4];
            ull a2[4] = { aA.x, aA.y, aB.x, aB.y };
            float4 f0 = *(const float4*)&Bs[s][k][tx * 4];
            float4 f1 = *(const float4*)&Bs[s][k][BH + tx * 4];
            ull b2[8];
            b2[0] = dup2(f0.x); b2[1] = dup2(f0.y); b2[2] = dup2(f0.z); b2[3] = dup2(f0.w);
            b2[4] = dup2(f1.x); b2[5] = dup2(f1.y); b2[6] = dup2(f1.z); b2[7] = dup2(f1.w);
#pragma unroll
            for (int i = 0; i < 4; i++) {
#pragma unroll
                for (int j = 0; j < 8; j++) fma2(c2[i][j], a2[i], b2[j]);
            }
        }
        if (c + 1 < NCHUNK) {
            const int t = s ^ 1;
            As[t][ac0 + 0][ar0] = av0.x; As[t][ac0 + 1][ar0] = av0.y;
            As[t][ac0 + 2][ar0] = av0.z; As[t][ac0 + 3][ar0] = av0.w;
            Bs[t][ac0 + 0][ar0] = bv0.x; Bs[t][ac0 + 1][ar0] = bv0.y;
            Bs[t][ac0 + 2][ar0] = bv0.z; Bs[t][ac0 + 3][ar0] = bv0.w;
            Bs[t][bc1 + 0][br1] = bv1.x; Bs[t][bc1 + 1][br1] = bv1.y;
            Bs[t][bc1 + 2][br1] = bv1.z; Bs[t][bc1 + 3][br1] = bv1.w;
            __syncthreads();
            s = t;
        }
    }

    float4 bv_lo, bv_hi;
    if (bias) {
        bv_lo = *(const float4*)&bias[col0 + tx * 4];
        bv_hi = *(const float4*)&bias[col0 + BH + tx * 4];
    }
#pragma unroll
    for (int i2 = 0; i2 < 4; i2++) {
        size_t r = (size_t)(row0 + ty * 8 + 2 * i2);
        float* rlo = C + r * (size_t)Ncols + col0;
        float* rhi = rlo + Ncols;
        float2 p0 = unpack2(c2[i2][0]);
        float2 p1 = unpack2(c2[i2][1]);
        float2 p2 = unpack2(c2[i2][2]);
        float2 p3 = unpack2(c2[i2][3]);
        float2 p4 = unpack2(c2[i2][4]);
        float2 p5 = unpack2(c2[i2][5]);
        float2 p6 = unpack2(c2[i2][6]);
        float2 p7 = unpack2(c2[i2][7]);
        float4 lo0, lo1, hi0, hi1;
        if (bias) {
            lo0 = make_float4(p0.x * scale + bv_lo.x, p1.x * scale + bv_lo.y,
                              p2.x * scale + bv_lo.z, p3.x * scale + bv_lo.w);
            hi0 = make_float4(p0.y * scale + bv_lo.x, p1.y * scale + bv_lo.y,
                              p2.y * scale + bv_lo.z, p3.y * scale + bv_lo.w);
            lo1 = make_float4(p4.x * scale + bv_hi.x, p5.x * scale + bv_hi.y,
                              p6.x * scale + bv_hi.z, p7.x * scale + bv_hi.w);
            hi1 = make_float4(p4.y * scale + bv_hi.x, p5.y * scale + bv_hi.y,
                              p6.y * scale + bv_hi.z, p7.y * scale + bv_hi.w);
        } else {
            lo0 = make_float4(p0.x * scale, p1.x * scale, p2.x * scale, p3.x * scale);
            hi0 = make_float4(p0.y * scale, p1.y * scale, p2.y * scale, p3.y * scale);
            lo1 = make_float4(p4.x * scale, p5.x * scale, p6.x * scale, p7.x * scale);
            hi1 = make_float4(p4.y * scale, p5.y * scale, p6.y * scale, p7.y * scale);
        }
        *(float4*)&rlo[tx * 4]      = lo0;
        *(float4*)&rlo[BH + tx * 4] = lo1;
        *(float4*)&rhi[tx * 4]      = hi0;
        *(float4*)&rhi[BH + tx * 4] = hi1;
    }
}

// ---------------------------------------------------------------------------
// Pos-gate stream + fused epilogue.
// R13 change: weights software-pipelined in REGISTERS at half-plane
// granularity. Per plane e: (1) load heads 8-15 of e into wB, (2) fma heads
// 0-7 from wA, (3) load heads 0-7 of e+1 into wA, (4) fma heads 8-15 from wB.
// Every LDS now has >=16 fma2 of slack before first use (was: LDS->fma2
// back-to-back, 29-cyc scoreboard stall on the critical path every plane).
// Regs: acc 32 + PE bufs 16 + wA/wB 32 + addr ~15 ≈ 110 < 128 (2 CTAs/SM).
// ---------------------------------------------------------------------------
#define PDEPTH 4

__global__ void __launch_bounds__(256, 2)
pos_epilogue_kernel(const float* __restrict__ PE, const float* __restrict__ Wg_w,
                    const float* __restrict__ Wg_b, float* __restrict__ out)
{
    __shared__ ull sh_wg2[EMB][HEADS];   // dup'd f32x2 per (e, h), 8 KB
    __shared__ float sh_b[HEADS];

    const int tid = threadIdx.x;
    for (int idx = tid; idx < EMB * HEADS; idx += 256) {
        int e = idx >> 4, h = idx & 15;
        sh_wg2[e][h] = dup2(Wg_w[h * EMB + e]);
    }
    if (tid < HEADS) sh_b[tid] = Wg_b[tid];
    __syncthreads();

    const int n = blockIdx.y;
    const int m = blockIdx.x * 1024 + tid * 4;

    const char* pe = (const char*)(PE + (size_t)n * MDIM + m);
    const size_t PLANE = (size_t)NDIM * MDIM * 4;   // bytes

    ull acc[HEADS][2];
#pragma unroll
    for (int h = 0; h < HEADS; h++) { acc[h][0] = 0ull; acc[h][1] = 0ull; }

    // depth-4 software pipeline of 16B streaming PE loads
    ull bx[PDEPTH], by[PDEPTH];
#pragma unroll
    for (int i = 0; i < PDEPTH; i++) ldcs_v2u64(pe + (size_t)i * PLANE, bx[i], by[i]);

    // weight register pipeline: wA = heads 0-7 of current plane,
    // wB = heads 8-15 of current plane (loaded inside the iteration).
    ull wA[8], wB[8];
    {
        const ulonglong2* wr = (const ulonglong2*)&sh_wg2[0][0];
        ulonglong2 t0 = wr[0], t1 = wr[1], t2 = wr[2], t3 = wr[3];
        wA[0] = t0.x; wA[1] = t0.y; wA[2] = t1.x; wA[3] = t1.y;
        wA[4] = t2.x; wA[5] = t2.y; wA[6] = t3.x; wA[7] = t3.y;
    }

#pragma unroll 4
    for (int e = 0; e < EMB; e++) {
        // (1) load heads 8-15 of plane e (used at step 4, >=16 fma2 later)
        {
            const ulonglong2* wr = (const ulonglong2*)&sh_wg2[e][8];
            ulonglong2 t0 = wr[0], t1 = wr[1], t2 = wr[2], t3 = wr[3];
            wB[0] = t0.x; wB[1] = t0.y; wB[2] = t1.x; wB[3] = t1.y;
            wB[4] = t2.x; wB[5] = t2.y; wB[6] = t3.x; wB[7] = t3.y;
        }
        ull pvx = bx[e & 3], pvy = by[e & 3];
        int en_ = e + PDEPTH;
        if (en_ < EMB) ldcs_v2u64(pe + (size_t)en_ * PLANE, bx[e & 3], by[e & 3]);

        // (2) fma heads 0-7 from wA (loaded a full plane ago)
#pragma unroll
        for (int h = 0; h < 8; h++) {
            fma2(acc[h][0], wA[h], pvx);
            fma2(acc[h][1], wA[h], pvy);
        }

        // (3) load heads 0-7 of plane e+1 (used next iteration)
        if (e + 1 < EMB) {
            const ulonglong2* wr = (const ulonglong2*)&sh_wg2[e + 1][0];
            ulonglong2 t0 = wr[0], t1 = wr[1], t2 = wr[2], t3 = wr[3];
            wA[0] = t0.x; wA[1] = t0.y; wA[2] = t1.x; wA[3] = t1.y;
            wA[4] = t2.x; wA[5] = t2.y; wA[6] = t3.x; wA[7] = t3.y;
        }

        // (4) fma heads 8-15 from wB (loaded >=16 fma2 ago)
#pragma unroll
        for (int h = 0; h < 8; h++) {
            fma2(acc[8 + h][0], wB[h], pvx);
            fma2(acc[8 + h][1], wB[h], pvy);
        }
    }

    const float4 av = *(const float4*)&g_aff[(size_t)n * MDIM + m];
    const float L2E = 1.4426950408889634f;
    float en0 = exp2f(-av.x * L2E);
    float en1 = exp2f(-av.y * L2E);
    float en2 = exp2f(-av.z * L2E);
    float en3 = exp2f(-av.w * L2E);

    float s0 = 0.f, s1 = 0.f, s2 = 0.f, s3 = 0.f;
#pragma unroll
    for (int h = 0; h < HEADS; h++) {
        float bh = sh_b[h];
        float2 p0 = unpack2(acc[h][0]);
        float2 p1 = unpack2(acc[h][1]);
        float w;
        w = fmaxf(p0.x + bh, 0.f) + 1e-6f; s0 += __fdividef(w, w + en0);
        w = fmaxf(p0.y + bh, 0.f) + 1e-6f; s1 += __fdividef(w, w + en1);
        w = fmaxf(p1.x + bh, 0.f) + 1e-6f; s2 += __fdividef(w, w + en2);
        w = fmaxf(p1.y + bh, 0.f) + 1e-6f; s3 += __fdividef(w, w + en3);
    }

    float4 o;
    o.x = (s0 > 8.0f) ? 1.0f : 0.0f;
    o.y = (s1 > 8.0f) ? 1.0f : 0.0f;
    o.z = (s2 > 8.0f) ? 1.0f : 0.0f;
    o.w = (s3 > 8.0f) ? 1.0f : 0.0f;
    *(float4*)&out[(size_t)n * MDIM + m] = o;
}

// ---------------------------------------------------------------------------
extern "C" void kernel_launch(void* const* d_in, const int* in_sizes, int n_in,
                              void* d_out, int out_size)
{
    (void)in_sizes; (void)n_in; (void)out_size;
    const float* ref_feat = (const float*)d_in[0];
    const float* sup_feat = (const float*)d_in[1];
    const float* PE       = (const float*)d_in[2];
    const float* Wg_w     = (const float*)d_in[3];
    const float* Wg_b     = (const float*)d_in[4];
    const float* Wq_w     = (const float*)d_in[5];
    const float* Wq_b     = (const float*)d_in[6];
    const float* Wk_w     = (const float*)d_in[7];
    const float* Wk_b     = (const float*)d_in[8];
    float* out = (float*)d_out;

    // fused q/k GEMM: z=0 -> q = ref@WqT+bq, z=1 -> k = sup@WkT+bk
    gemm_nt_kernel<<<dim3(DDIM / BN, NDIM / BM, 2), 512>>>(
        ref_feat, Wq_w, Wq_b, sup_feat, Wk_w, Wk_b, DDIM, 1.0f, 0);
    // aff = (q @ kT) / 32
    gemm_nt_kernel<<<dim3(MDIM / BN, NDIM / BM, 1), 512>>>(
        nullptr, nullptr, nullptr, nullptr, nullptr, nullptr, MDIM, 0.03125f, 2);
    // pos stream + fused epilogue
    pos_epilogue_kernel<<<dim3(MDIM / 1024, NDIM), 256>>>(PE, Wg_w, Wg_b, out);
}

// round 15
// speedup vs baseline: 1.5241x; 1.0709x over previous
#include <cuda_runtime.h>
#include <cstdint>

// ---------------------------------------------------------------------------
// AdjGenerator: adj = (mean_h sigmoid(log(relu(Wg·PE)+1e-6) + (q·kT)/32) > 0.5)
// N = M = 2048, D = 1024, EMB = 64, HEADS = 16
// R15: pos kernel PE prefetch via cp.async smem ring (depth 8), pairwise
//      sigmoid epilogue. tcgen05 route closed (harness targets compute_103).
// ---------------------------------------------------------------------------

#define NDIM 2048
#define MDIM 2048
#define DDIM 1024
#define EMB  64
#define HEADS 16

__device__ float g_q[NDIM * DDIM];
__device__ float g_k[MDIM * DDIM];
__device__ float g_aff[NDIM * MDIM];

typedef unsigned long long ull;

// ---- packed f32x2 helpers (Blackwell FFMA2, PTX-only) ---------------------
__device__ __forceinline__ ull dup2(float v) {
    ull r;
    asm("mov.b64 %0, {%1, %1};" : "=l"(r) : "f"(v));
    return r;
}
__device__ __forceinline__ void fma2(ull& d, ull a, ull b) {
    asm("fma.rn.f32x2 %0, %1, %2, %0;" : "+l"(d) : "l"(a), "l"(b));
}
__device__ __forceinline__ float2 unpack2(ull v) {
    float2 f;
    asm("mov.b64 {%0, %1}, %2;" : "=f"(f.x), "=f"(f.y) : "l"(v));
    return f;
}
__device__ __forceinline__ uint32_t smem_u32(const void* p) {
    uint32_t a;
    asm("{ .reg .u64 t; cvta.to.shared.u64 t, %1; cvt.u32.u64 %0, t; }" : "=r"(a) : "l"(p));
    return a;
}
__device__ __forceinline__ void cp_async16(uint32_t saddr, const void* gptr) {
    asm volatile("cp.async.cg.shared.global [%0], [%1], 16;"
                 :: "r"(saddr), "l"(gptr) : "memory");
}
#define CP_COMMIT() asm volatile("cp.async.commit_group;" ::: "memory")
#define CP_WAIT(n)  asm volatile("cp.async.wait_group %0;" :: "n"(n) : "memory")

// ---------------------------------------------------------------------------
// SGEMM NT (verified ~164us/launch, ~88% of scalar FFMA2 floor).
// 512 threads, BM=128, BN=256, BK=16, row-packed f32x2 accumulators,
// float B smem with reg-side dup (alu pipe), double-buffered, 1 bar/chunk.
// ---------------------------------------------------------------------------
#define BM 128
#define BN 256
#define BK 16
#define BH 128
#define NCHUNK (DDIM / BK)

__global__ void __launch_bounds__(512, 1)
gemm_nt_kernel(const float* __restrict__ A0, const float* __restrict__ B0,
               const float* __restrict__ bias0,
               const float* __restrict__ A1, const float* __restrict__ B1,
               const float* __restrict__ bias1,
               int Ncols, float scale, int outsel)
{
    const float* A;
    const float* B;
    const float* bias;
    float* C;
    if (outsel == 0) {
        if (blockIdx.z == 0) { A = A0; B = B0; bias = bias0; C = g_q; }
        else                 { A = A1; B = B1; bias = bias1; C = g_k; }
    } else {
        A = g_q; B = g_k; bias = nullptr; C = g_aff;
    }

    const int K = DDIM;

    __shared__ float As[2][BK][BM + 4];
    __shared__ float Bs[2][BK][BN + 4];

    const int tid = threadIdx.x;
    const int tx = tid & 31;
    const int ty = tid >> 5;
    const int row0 = blockIdx.y * BM;
    const int col0 = blockIdx.x * BN;

    const float* Abase = A + (size_t)row0 * K;
    const float* Bbase = B + (size_t)col0 * K;

    const int ar0 = tid >> 2,          ac0 = (tid & 3) * 4;
    const int br1 = (tid + 512) >> 2,  bc1 = ((tid + 512) & 3) * 4;

    float4 av0 = *(const float4*)&Abase[(size_t)ar0 * K + ac0];
    float4 bv0 = *(const float4*)&Bbase[(size_t)ar0 * K + ac0];
    float4 bv1 = *(const float4*)&Bbase[(size_t)br1 * K + bc1];

    As[0][ac0 + 0][ar0] = av0.x; As[0][ac0 + 1][ar0] = av0.y;
    As[0][ac0 + 2][ar0] = av0.z; As[0][ac0 + 3][ar0] = av0.w;
    Bs[0][ac0 + 0][ar0] = bv0.x; Bs[0][ac0 + 1][ar0] = bv0.y;
    Bs[0][ac0 + 2][ar0] = bv0.z; Bs[0][ac0 + 3][ar0] = bv0.w;
    Bs[0][bc1 + 0][br1] = bv1.x; Bs[0][bc1 + 1][br1] = bv1.y;
    Bs[0][bc1 + 2][br1] = bv1.z; Bs[0][bc1 + 3][br1] = bv1.w;
    __syncthreads();

    ull c2[4][8];
#pragma unroll
    for (int i = 0; i < 4; i++)
#pragma unroll
        for (int j = 0; j < 8; j++) c2[i][j] = 0ull;

    int s = 0;
    for (int c = 0; c < NCHUNK; c++) {
        const int kc = (c + 1) * BK;
        if (c + 1 < NCHUNK) {
            av0 = *(const float4*)&Abase[(size_t)ar0 * K + kc + ac0];
            bv0 = *(const float4*)&Bbase[(size_t)ar0 * K + kc + ac0];
            bv1 = *(const float4*)&Bbase[(size_t)br1 * K + kc + bc1];
        }
#pragma unroll
        for (int k = 0; k < BK; k++) {
            ulonglong2 aA = *(const ulonglong2*)&As[s][k][ty * 8];
            ulonglong2 aB = *(const ulonglong2*)&As[s][k][ty * 8 + 4];
            ull a2[4] = { aA.x, aA.y, aB.x, aB.y };
            float4 f0 = *(const float4*)&Bs[s][k][tx * 4];
            float4 f1 = *(const float4*)&Bs[s][k][BH + tx * 4];
            ull b2[8];
            b2[0] = dup2(f0.x); b2[1] = dup2(f0.y); b2[2] = dup2(f0.z); b2[3] = dup2(f0.w);
            b2[4] = dup2(f1.x); b2[5] = dup2(f1.y); b2[6] = dup2(f1.z); b2[7] = dup2(f1.w);
#pragma unroll
            for (int i = 0; i < 4; i++) {
#pragma unroll
                for (int j = 0; j < 8; j++) fma2(c2[i][j], a2[i], b2[j]);
            }
        }
        if (c + 1 < NCHUNK) {
            const int t = s ^ 1;
            As[t][ac0 + 0][ar0] = av0.x; As[t][ac0 + 1][ar0] = av0.y;
            As[t][ac0 + 2][ar0] = av0.z; As[t][ac0 + 3][ar0] = av0.w;
            Bs[t][ac0 + 0][ar0] = bv0.x; Bs[t][ac0 + 1][ar0] = bv0.y;
            Bs[t][ac0 + 2][ar0] = bv0.z; Bs[t][ac0 + 3][ar0] = bv0.w;
            Bs[t][bc1 + 0][br1] = bv1.x; Bs[t][bc1 + 1][br1] = bv1.y;
            Bs[t][bc1 + 2][br1] = bv1.z; Bs[t][bc1 + 3][br1] = bv1.w;
            __syncthreads();
            s = t;
        }
    }

    float4 bv_lo, bv_hi;
    if (bias) {
        bv_lo = *(const float4*)&bias[col0 + tx * 4];
        bv_hi = *(const float4*)&bias[col0 + BH + tx * 4];
    }
#pragma unroll
    for (int i2 = 0; i2 < 4; i2++) {
        size_t r = (size_t)(row0 + ty * 8 + 2 * i2);
        float* rlo = C + r * (size_t)Ncols + col0;
        float* rhi = rlo + Ncols;
        float2 p0 = unpack2(c2[i2][0]);
        float2 p1 = unpack2(c2[i2][1]);
        float2 p2 = unpack2(c2[i2][2]);
        float2 p3 = unpack2(c2[i2][3]);
        float2 p4 = unpack2(c2[i2][4]);
        float2 p5 = unpack2(c2[i2][5]);
        float2 p6 = unpack2(c2[i2][6]);
        float2 p7 = unpack2(c2[i2][7]);
        float4 lo0, lo1, hi0, hi1;
        if (bias) {
            lo0 = make_float4(p0.x * scale + bv_lo.x, p1.x * scale + bv_lo.y,
                              p2.x * scale + bv_lo.z, p3.x * scale + bv_lo.w);
            hi0 = make_float4(p0.y * scale + bv_lo.x, p1.y * scale + bv_lo.y,
                              p2.y * scale + bv_lo.z, p3.y * scale + bv_lo.w);
            lo1 = make_float4(p4.x * scale + bv_hi.x, p5.x * scale + bv_hi.y,
                              p6.x * scale + bv_hi.z, p7.x * scale + bv_hi.w);
            hi1 = make_float4(p4.y * scale + bv_hi.x, p5.y * scale + bv_hi.y,
                              p6.y * scale + bv_hi.z, p7.y * scale + bv_hi.w);
        } else {
            lo0 = make_float4(p0.x * scale, p1.x * scale, p2.x * scale, p3.x * scale);
            hi0 = make_float4(p0.y * scale, p1.y * scale, p2.y * scale, p3.y * scale);
            lo1 = make_float4(p4.x * scale, p5.x * scale, p6.x * scale, p7.x * scale);
            hi1 = make_float4(p4.y * scale, p5.y * scale, p6.y * scale, p7.y * scale);
        }
        *(float4*)&rlo[tx * 4]      = lo0;
        *(float4*)&rlo[BH + tx * 4] = lo1;
        *(float4*)&rhi[tx * 4]      = hi0;
        *(float4*)&rhi[BH + tx * 4] = hi1;
    }
}

// ---------------------------------------------------------------------------
// Pos-gate stream + fused epilogue.
// R15: PE prefetch via cp.async -> per-thread SMEM ring, depth 8 (32 KB/CTA,
// 128 B/thread outstanding vs 64 B register-limited before). Each thread
// reads ONLY its own 16B slot -> no __syncthreads in the loop; one commit
// per plane keeps per-thread wait_group(7) exactly tracking plane arrival.
// Weight pipeline in registers (R13, verified). Pairwise sigmoid epilogue:
// sig(a)+sig(b) = (2ab+E(a+b)) / ((a+E)(b+E))  -> 8 divides per element.
// Regs ~115 < 128 -> 2 CTAs/SM.
// ---------------------------------------------------------------------------
#define RDEPTH 8

__global__ void __launch_bounds__(256, 2)
pos_epilogue_kernel(const float* __restrict__ PE, const float* __restrict__ Wg_w,
                    const float* __restrict__ Wg_b, float* __restrict__ out)
{
    __shared__ ull sh_wg2[EMB][HEADS];          // 8 KB
    __shared__ float sh_b[HEADS];
    __shared__ ull ring[RDEPTH * 256 * 2];      // 32 KB: stage stride 4096 B

    const int tid = threadIdx.x;
    for (int idx = tid; idx < EMB * HEADS; idx += 256) {
        int e = idx >> 4, h = idx & 15;
        sh_wg2[e][h] = dup2(Wg_w[h * EMB + e]);
    }
    if (tid < HEADS) sh_b[tid] = Wg_b[tid];
    __syncthreads();

    const int n = blockIdx.y;
    const int m = blockIdx.x * 1024 + tid * 4;

    const char* pe = (const char*)(PE + (size_t)n * MDIM + m);
    const size_t PLANE = (size_t)NDIM * MDIM * 4;   // bytes

    const uint32_t myslot = smem_u32(&ring[tid * 2]);   // my 16B in stage 0

    ull acc[HEADS][2];
#pragma unroll
    for (int h = 0; h < HEADS; h++) { acc[h][0] = 0ull; acc[h][1] = 0ull; }

    // prologue: planes 0..7 in flight, one group per plane
#pragma unroll
    for (int i = 0; i < RDEPTH; i++) {
        cp_async16(myslot + i * 4096, pe + (size_t)i * PLANE);
        CP_COMMIT();
    }

    // weight register pipeline (R13): wA = heads 0-7 current, wB = 8-15
    ull wA[8], wB[8];
    {
        const ulonglong2* wr = (const ulonglong2*)&sh_wg2[0][0];
        ulonglong2 t0 = wr[0], t1 = wr[1], t2 = wr[2], t3 = wr[3];
        wA[0] = t0.x; wA[1] = t0.y; wA[2] = t1.x; wA[3] = t1.y;
        wA[4] = t2.x; wA[5] = t2.y; wA[6] = t3.x; wA[7] = t3.y;
    }

#pragma unroll 8
    for (int e = 0; e < EMB; e++) {
        // plane e guaranteed arrived when <= RDEPTH-1 groups pending
        CP_WAIT(RDEPTH - 1);
        ull pvx, pvy;
        asm volatile("ld.shared.v2.u64 {%0, %1}, [%2];"
                     : "=l"(pvx), "=l"(pvy) : "r"(myslot + (e & 7) * 4096));

        // refill this stage with plane e+8 (same-thread slot: no sync needed)
        int en_ = e + RDEPTH;
        if (en_ < EMB) cp_async16(myslot + (e & 7) * 4096, pe + (size_t)en_ * PLANE);
        CP_COMMIT();   // always commit: keeps group count = 1/plane

        // load heads 8-15 of plane e (consumed after 16 fma2)
        {
            const ulonglong2* wr = (const ulonglong2*)&sh_wg2[e][8];
            ulonglong2 t0 = wr[0], t1 = wr[1], t2 = wr[2], t3 = wr[3];
            wB[0] = t0.x; wB[1] = t0.y; wB[2] = t1.x; wB[3] = t1.y;
            wB[4] = t2.x; wB[5] = t2.y; wB[6] = t3.x; wB[7] = t3.y;
        }
#pragma unroll
        for (int h = 0; h < 8; h++) {
            fma2(acc[h][0], wA[h], pvx);
            fma2(acc[h][1], wA[h], pvy);
        }
        if (e + 1 < EMB) {
            const ulonglong2* wr = (const ulonglong2*)&sh_wg2[e + 1][0];
            ulonglong2 t0 = wr[0], t1 = wr[1], t2 = wr[2], t3 = wr[3];
            wA[0] = t0.x; wA[1] = t0.y; wA[2] = t1.x; wA[3] = t1.y;
            wA[4] = t2.x; wA[5] = t2.y; wA[6] = t3.x; wA[7] = t3.y;
        }
#pragma unroll
        for (int h = 0; h < 8; h++) {
            fma2(acc[8 + h][0], wB[h], pvx);
            fma2(acc[8 + h][1], wB[h], pvy);
        }
    }

    // epilogue: E = exp(-aff); pairwise sigmoid sums (8 divides/element)
    const float4 av = *(const float4*)&g_aff[(size_t)n * MDIM + m];
    const float L2E = 1.4426950408889634f;
    float E[4];
    E[0] = exp2f(-av.x * L2E);
    E[1] = exp2f(-av.y * L2E);
    E[2] = exp2f(-av.z * L2E);
    E[3] = exp2f(-av.w * L2E);

    float w[HEADS][4];
#pragma unroll
    for (int h = 0; h < HEADS; h++) {
        float bh = sh_b[h];
        float2 p0 = unpack2(acc[h][0]);
        float2 p1 = unpack2(acc[h][1]);
        w[h][0] = fmaxf(p0.x + bh, 0.f) + 1e-6f;
        w[h][1] = fmaxf(p0.y + bh, 0.f) + 1e-6f;
        w[h][2] = fmaxf(p1.x + bh, 0.f) + 1e-6f;
        w[h][3] = fmaxf(p1.y + bh, 0.f) + 1e-6f;
    }

    float4 o;
    float* op = &o.x;
#pragma unroll
    for (int j = 0; j < 4; j++) {
        float Ej = E[j];
        float s = 0.f;
#pragma unroll
        for (int p = 0; p < 8; p++) {
            float a = w[2 * p][j], b = w[2 * p + 1][j];
            float ab = a * b;
            float num = fmaf(Ej, a + b, 2.0f * ab);
            float den = fmaf(a + Ej, b, (a + Ej) * Ej);   // (a+E)(b+E)
            s += __fdividef(num, den);
        }
        op[j] = (s > 8.0f) ? 1.0f : 0.0f;
    }
    *(float4*)&out[(size_t)n * MDIM + m] = o;
}

// ---------------------------------------------------------------------------
extern "C" void kernel_launch(void* const* d_in, const int* in_sizes, int n_in,
                              void* d_out, int out_size)
{
    (void)in_sizes; (void)n_in; (void)out_size;
    const float* ref_feat = (const float*)d_in[0];
    const float* sup_feat = (const float*)d_in[1];
    const float* PE       = (const float*)d_in[2];
    const float* Wg_w     = (const float*)d_in[3];
    const float* Wg_b     = (const float*)d_in[4];
    const float* Wq_w     = (const float*)d_in[5];
    const float* Wq_b     = (const float*)d_in[6];
    const float* Wk_w     = (const float*)d_in[7];
    const float* Wk_b     = (const float*)d_in[8];
    float* out = (float*)d_out;

    // fused q/k GEMM: z=0 -> q = ref@WqT+bq, z=1 -> k = sup@WkT+bk
    gemm_nt_kernel<<<dim3(DDIM / BN, NDIM / BM, 2), 512>>>(
        ref_feat, Wq_w, Wq_b, sup_feat, Wk_w, Wk_b, DDIM, 1.0f, 0);
    // aff = (q @ kT) / 32
    gemm_nt_kernel<<<dim3(MDIM / BN, NDIM / BM, 1), 512>>>(
        nullptr, nullptr, nullptr, nullptr, nullptr, nullptr, MDIM, 0.03125f, 2);
    // pos stream + fused epilogue
    pos_epilogue_kernel<<<dim3(MDIM / 1024, NDIM), 256>>>(PE, Wg_w, Wg_b, out);
}